// round 7
// baseline (speedup 1.0000x reference)
#include <cuda_runtime.h>
#include <cuda_fp16.h>
#include <math.h>
#include <stdint.h>

// ---------------- problem constants ----------------
#define BB   4
#define NSP  1500
#define NN   6000          // BB*NSP
#define EE   120000
#define HH   384
#define HWPX (HH*HH)       // 147456
#define NPX  (BB*HWPX)     // 589824
#define HS   96
#define HWI  (HS*HS)       // 9216
#define CC   256
#define NPOOL 512          // feats0 | feats1 columns
#define NENT (4*NPX)       // 2359296 pooling entries
#define CSR_E (EE+NN)      // folded self loops: one entry each, weight 2*dis^2
#define SIGMA_INV 5.0f     // 1/0.2

// ---------------- scratch (device globals; k_init re-inits every call) ----------
__device__ __half g_Bmh[(size_t)BB*HWI*NPOOL];   // 37.7 MB feats NHWC fp16, stacked
__device__ int4  g_ent4[NENT/2];                 // packed (row,w) pairs, 18.9 MB
__device__ float g_pool[(size_t)NN*NPOOL];
__device__ float g_Za[NN*CC];
__device__ float g_Zb[NN*CC];
__device__ float g_xw[NN*CC];
__device__ float g_cnt[NN];
__device__ float g_sumI[NN*3];
__device__ float g_deg[NN];      // self-loop +2 folded into dis computation
__device__ float g_dis[NN];
__device__ float g_wnn[EE];
__device__ int   g_icnt[NN];
__device__ int   g_ecnt[NN];     // +1 self slot folded into scanE
__device__ int   g_eoff[NN+1];
__device__ int   g_poff[NN+1];
__device__ int   g_efill[NN];
__device__ int   g_pfill[NN];
__device__ int   g_csr_src[CSR_E];
__device__ float g_csr_nrm[CSR_E];
__device__ float g_wn[15*CC];

// ---------------- 0: init (self-healing regardless of prior stream state) -------
__global__ void k_init() {
    int i = blockIdx.x*blockDim.x + threadIdx.x;
    if (i >= NN) return;
    g_icnt[i] = 0; g_ecnt[i] = 0;
    g_efill[i] = 0; g_pfill[i] = 0;
    g_deg[i] = 0.f;
    g_sumI[i*3+0] = 0.f; g_sumI[i*3+1] = 0.f; g_sumI[i*3+2] = 0.f;
}

// ---------------- 1: counts + image sums ----------------
__global__ void k_build1(const int* __restrict__ labels, const float* __restrict__ image) {
    int p = blockIdx.x*blockDim.x + threadIdx.x;
    if (p >= NPX) return;
    int b  = p / HWPX;
    int yx = p % HWPX;
    int s = b*NSP + labels[p];
    atomicAdd(&g_icnt[s], 1);
    atomicAdd(&g_sumI[s*3+0], image[(size_t)(b*3+0)*HWPX + yx]);
    atomicAdd(&g_sumI[s*3+1], image[(size_t)(b*3+1)*HWPX + yx]);
    atomicAdd(&g_sumI[s*3+2], image[(size_t)(b*3+2)*HWPX + yx]);
}

// ---------------- 2: feats transpose NCHW -> fp16 (b*9216, 512) ------------------
// 32q x 32c tile in smem; store phase packs 4 halves -> one uint2 per thread.
__global__ void k_transpose(const float* __restrict__ f0, const float* __restrict__ f1) {
    __shared__ float t[32][33];
    int z = blockIdx.z;                 // 0..7
    int b = z & 3;
    int colOff = (z >> 2) * CC;
    const float* __restrict__ src = (z < 4) ? f0 : f1;
    int q0 = blockIdx.x*32, c0 = blockIdx.y*32;
    int tx = threadIdx.x, ty = threadIdx.y;     // 32 x 8
    #pragma unroll
    for (int i = 0; i < 32; i += 8) {
        int c = c0 + ty + i, q = q0 + tx;
        t[ty+i][tx] = src[((size_t)b*CC + c)*HWI + q];
    }
    __syncthreads();
    // 256 threads: tid -> (qrow = tid>>3, cg = tid&7); one uint2 (4 halves) each
    int tid = ty*32 + tx;
    int qrow = tid >> 3, cg = tid & 7;
    __half2 h0 = __floats2half2_rn(t[cg*4+0][qrow], t[cg*4+1][qrow]);
    __half2 h1 = __floats2half2_rn(t[cg*4+2][qrow], t[cg*4+3][qrow]);
    uint2 o;
    o.x = *reinterpret_cast<unsigned*>(&h0);
    o.y = *reinterpret_cast<unsigned*>(&h1);
    size_t base = ((size_t)b*HWI + q0 + qrow)*NPOOL + colOff + c0 + cg*4;
    *reinterpret_cast<uint2*>(&g_Bmh[base]) = o;
}

// ---------------- 3: scan pooling counts (warp-shuffle) + cnt float --------------
__global__ void k_scanP() {
    __shared__ int wsum[32];
    int t = threadIdx.x, lane = t & 31, w = t >> 5;
    int loc[6]; int s = 0;
    #pragma unroll
    for (int i = 0; i < 6; i++) {
        int idx = t*6 + i;
        int v = (idx < NN) ? 4*g_icnt[idx] : 0;
        loc[i] = s; s += v;
        if (idx < NN) g_cnt[idx] = (float)(v >> 2);
    }
    int x = s;
    #pragma unroll
    for (int o = 1; o < 32; o <<= 1) {
        int y = __shfl_up_sync(0xffffffffu, x, o);
        if (lane >= o) x += y;
    }
    if (lane == 31) wsum[w] = x;
    __syncthreads();
    if (w == 0) {
        int y = wsum[lane];
        #pragma unroll
        for (int o = 1; o < 32; o <<= 1) {
            int z2 = __shfl_up_sync(0xffffffffu, y, o);
            if (lane >= o) y += z2;
        }
        wsum[lane] = y;
    }
    __syncthreads();
    int base = (w > 0 ? wsum[w-1] : 0) + x - s;   // exclusive prefix of this thread
    #pragma unroll
    for (int i = 0; i < 6; i++) {
        int idx = t*6 + i;
        if (idx < NN) g_poff[idx] = base + loc[i];
    }
    if (t == 1023) g_poff[NN] = base + s;
}

// ---------------- 4: pooling entries (CSR by superpixel) ----------------
__global__ void k_build2(const int* __restrict__ labels) {
    int p = blockIdx.x*blockDim.x + threadIdx.x;
    if (p >= NPX) return;
    int b  = p / HWPX;
    int yx = p % HWPX;
    int y = yx / HH, x = yx % HH;
    int s = b*NSP + labels[p];

    const float scale = 95.0f/383.0f;
    float fy = y*scale, fx = x*scale;
    int y0 = (int)floorf(fy); if (y0 > 95) y0 = 95;
    int x0 = (int)floorf(fx); if (x0 > 95) x0 = 95;
    float wy = fy - y0, wx = fx - x0;
    int y1 = min(y0+1, 95), x1 = min(x0+1, 95);

    int base = b*HWI;
    int pos = g_poff[s] + atomicAdd(&g_pfill[s], 4);   // pos % 4 == 0
    int4 a, bb;
    a.x  = base + y0*HS + x0;  a.y  = __float_as_int((1.f-wy)*(1.f-wx));
    a.z  = base + y0*HS + x1;  a.w  = __float_as_int((1.f-wy)*wx);
    bb.x = base + y1*HS + x0;  bb.y = __float_as_int(wy*(1.f-wx));
    bb.z = base + y1*HS + x1;  bb.w = __float_as_int(wy*wx);
    g_ent4[(pos>>1)+0] = a;
    g_ent4[(pos>>1)+1] = bb;
}

// ---------------- 5: sparse pooling SpMM ----------------
// 256 thr = 4 teams x 64 lanes; lane owns 8 cols via one uint4 (8 fp16) load.
__device__ __forceinline__ void acc8(float* acc, float w, uint4 v) {
    float2 f0 = __half22float2(*(const __half2*)&v.x);
    float2 f1 = __half22float2(*(const __half2*)&v.y);
    float2 f2 = __half22float2(*(const __half2*)&v.z);
    float2 f3 = __half22float2(*(const __half2*)&v.w);
    acc[0] = fmaf(w, f0.x, acc[0]); acc[1] = fmaf(w, f0.y, acc[1]);
    acc[2] = fmaf(w, f1.x, acc[2]); acc[3] = fmaf(w, f1.y, acc[3]);
    acc[4] = fmaf(w, f2.x, acc[4]); acc[5] = fmaf(w, f2.y, acc[5]);
    acc[6] = fmaf(w, f3.x, acc[6]); acc[7] = fmaf(w, f3.y, acc[7]);
}

__global__ void k_spmm() {
    __shared__ int2  sh[256];
    __shared__ float red[4][512];
    int s = blockIdx.x;
    int tid = threadIdx.x;
    int team = tid >> 6, lane = tid & 63;
    int beg = g_poff[s], end = g_poff[s+1];
    const uint4* __restrict__ B4 = reinterpret_cast<const uint4*>(g_Bmh);
    const int2* __restrict__ ent = reinterpret_cast<const int2*>(g_ent4);
    float acc[8];
    #pragma unroll
    for (int i = 0; i < 8; i++) acc[i] = 0.f;

    for (int c0 = beg; c0 < end; c0 += 256) {
        int m = min(256, end - c0);
        __syncthreads();
        if (tid < m) sh[tid] = ent[c0 + tid];
        __syncthreads();
        int j = team;
        for (; j + 4 < m; j += 8) {
            int2 e0 = sh[j], e1 = sh[j+4];
            uint4 v0 = B4[(size_t)e0.x*64 + lane];
            uint4 v1 = B4[(size_t)e1.x*64 + lane];
            acc8(acc, __int_as_float(e0.y), v0);
            acc8(acc, __int_as_float(e1.y), v1);
        }
        if (j < m) {
            int2 e0 = sh[j];
            uint4 v0 = B4[(size_t)e0.x*64 + lane];
            acc8(acc, __int_as_float(e0.y), v0);
        }
    }
    #pragma unroll
    for (int i = 0; i < 8; i++) red[team][lane*8+i] = acc[i];
    __syncthreads();
    #pragma unroll
    for (int c = tid; c < 512; c += 256)
        g_pool[(size_t)s*NPOOL + c] = red[0][c] + red[1][c] + red[2][c] + red[3][c];
}

// ---------------- 6: edge weights + degree + per-dst counts ----------------
__global__ void k_edge_w_deg(const int* __restrict__ edges, const float* __restrict__ probas) {
    int e = blockIdx.x*blockDim.x + threadIdx.x;
    if (e >= EE) return;
    int src = edges[e], dst = edges[EE + e];
    float w = expf(-fabsf(probas[src] - probas[dst]) * SIGMA_INV);
    g_wnn[e] = w;
    atomicAdd(&g_deg[dst], w);
    atomicAdd(&g_ecnt[dst], 1);
}

// ---------------- 7: scan edge counts (+1 self slot, warp-shuffle) + dis ---------
__global__ void k_scanE() {
    __shared__ int wsum[32];
    int t = threadIdx.x, lane = t & 31, w = t >> 5;
    int loc[6]; int s = 0;
    #pragma unroll
    for (int i = 0; i < 6; i++) {
        int idx = t*6 + i;
        int v = (idx < NN) ? (g_ecnt[idx] + 1) : 0;
        loc[i] = s; s += v;
        if (idx < NN) {
            float d = g_deg[idx] + 2.0f;
            g_dis[idx] = rsqrtf(fmaxf(d, 1e-30f));
        }
    }
    int x = s;
    #pragma unroll
    for (int o = 1; o < 32; o <<= 1) {
        int y = __shfl_up_sync(0xffffffffu, x, o);
        if (lane >= o) x += y;
    }
    if (lane == 31) wsum[w] = x;
    __syncthreads();
    if (w == 0) {
        int y = wsum[lane];
        #pragma unroll
        for (int o = 1; o < 32; o <<= 1) {
            int z2 = __shfl_up_sync(0xffffffffu, y, o);
            if (lane >= o) y += z2;
        }
        wsum[lane] = y;
    }
    __syncthreads();
    int base = (w > 0 ? wsum[w-1] : 0) + x - s;
    #pragma unroll
    for (int i = 0; i < 6; i++) {
        int idx = t*6 + i;
        if (idx < NN) g_eoff[idx] = base + loc[i];
    }
    if (t == 1023) g_eoff[NN] = base + s;
}

// ---------------- 8: edge CSR scatter (self loop -> last slot, no atomic) ------
__global__ void k_edge_scatter(const int* __restrict__ edges) {
    int i = blockIdx.x*blockDim.x + threadIdx.x;
    if (i >= EE + NN) return;
    if (i < EE) {
        int src = edges[i], dst = edges[EE + i];
        float w = g_wnn[i];
        int j = g_eoff[dst] + atomicAdd(&g_efill[dst], 1);
        g_csr_src[j] = src;
        g_csr_nrm[j] = g_dis[src] * w * g_dis[dst];
    } else {
        int n = i - EE;
        int j = g_eoff[n+1] - 1;
        g_csr_src[j] = n;
        g_csr_nrm[j] = 2.0f * g_dis[n] * g_dis[n];
    }
}

// ---------------- GCN ----------------
__global__ void k_x0(const float* __restrict__ W0) {   // xw = (sumI/cnt) @ W0 (K=3)
    __shared__ float z0[3];
    int n = blockIdx.x, c = threadIdx.x;
    if (c < 3) z0[c] = g_sumI[n*3+c] / fmaxf(g_cnt[n], 1.0f);
    __syncthreads();
    g_xw[(size_t)n*CC + c] = z0[0]*W0[c] + z0[1]*W0[CC+c] + z0[2]*W0[2*CC+c];
}

// 256 thr = 4 teams x 64 lanes; lane owns 4 cols via float4. grid = NN/4.
__global__ void k_agg_relu(const float* __restrict__ xw, const float* __restrict__ bias,
                           float* __restrict__ out) {
    int tid = threadIdx.x;
    int team = tid >> 6, lane = tid & 63;
    int n = blockIdx.x*4 + team;
    const float4* __restrict__ xw4 = reinterpret_cast<const float4*>(xw);
    float4 bv = reinterpret_cast<const float4*>(bias)[lane];
    int s = g_eoff[n], e = g_eoff[n+1];
    float4 acc = make_float4(0.f,0.f,0.f,0.f);
    for (int j = s; j < e; j++) {
        int   sc = __ldg(&g_csr_src[j]);
        float nr = __ldg(&g_csr_nrm[j]);
        float4 v = xw4[(size_t)sc*64 + lane];
        acc.x = fmaf(nr, v.x, acc.x); acc.y = fmaf(nr, v.y, acc.y);
        acc.z = fmaf(nr, v.z, acc.z); acc.w = fmaf(nr, v.w, acc.w);
    }
    float4 r;
    r.x = fmaxf(acc.x + bv.x, 0.f); r.y = fmaxf(acc.y + bv.y, 0.f);
    r.z = fmaxf(acc.z + bv.z, 0.f); r.w = fmaxf(acc.w + bv.w, 0.f);
    reinterpret_cast<float4*>(out)[(size_t)n*64 + lane] = r;
}

// grid 1500 x 256 thr, float4 per thread
__global__ void k_mix(const float* __restrict__ Zin, float* __restrict__ Zout, int off4) {
    int i = blockIdx.x*256 + threadIdx.x;          // 0..383999
    int n = i >> 6, c4 = i & 63;
    float4 hp = reinterpret_cast<const float4*>(g_pool)[(size_t)n*128 + off4 + c4];
    float4 z  = reinterpret_cast<const float4*>(Zin)[(size_t)n*64 + c4];
    float inv = 0.5f / fmaxf(g_cnt[n], 1.0f);
    float4 r;
    r.x = hp.x*inv + 0.5f*z.x; r.y = hp.y*inv + 0.5f*z.y;
    r.z = hp.z*inv + 0.5f*z.z; r.w = hp.w*inv + 0.5f*z.w;
    reinterpret_cast<float4*>(Zout)[(size_t)n*64 + c4] = r;
}

// ---------------- SGEMM: C = A(MxK) * B(KxN), row-major, BM=128 BN=64 BK=8 ------
__global__ void k_sgemm(const float* __restrict__ A, const float* __restrict__ B,
                        float* __restrict__ C, int M, int N, int K,
                        int lda, int ldb, int ldc) {
    __shared__ float As[8][128];
    __shared__ float Bs[8][64];
    int tid = threadIdx.x;
    int tx = tid & 15, ty = tid >> 4;
    int m0 = blockIdx.y*128, n0 = blockIdx.x*64;
    float acc[8][4];
    #pragma unroll
    for (int i=0;i<8;i++)
        #pragma unroll
        for (int j=0;j<4;j++) acc[i][j]=0.f;

    int a_m = tid >> 1;
    int a_k = (tid & 1) * 4;
    int b_k = tid >> 5;
    int b_n = (tid & 31) * 2;

    for (int kt = 0; kt < K; kt += 8) {
        float4 av = make_float4(0.f,0.f,0.f,0.f);
        if (m0 + a_m < M)
            av = *reinterpret_cast<const float4*>(A + (size_t)(m0+a_m)*lda + kt + a_k);
        As[a_k+0][a_m]=av.x; As[a_k+1][a_m]=av.y;
        As[a_k+2][a_m]=av.z; As[a_k+3][a_m]=av.w;
        float2 bv = *reinterpret_cast<const float2*>(B + (size_t)(kt+b_k)*ldb + n0 + b_n);
        Bs[b_k][b_n]=bv.x; Bs[b_k][b_n+1]=bv.y;
        __syncthreads();
        #pragma unroll
        for (int k = 0; k < 8; k++) {
            float ar[8], br[4];
            #pragma unroll
            for (int i=0;i<8;i++) ar[i]=As[k][ty*8+i];
            #pragma unroll
            for (int j=0;j<4;j++) br[j]=Bs[k][tx*4+j];
            #pragma unroll
            for (int i=0;i<8;i++)
                #pragma unroll
                for (int j=0;j<4;j++) acc[i][j] = fmaf(ar[i], br[j], acc[i][j]);
        }
        __syncthreads();
    }
    #pragma unroll
    for (int i = 0; i < 8; i++) {
        int m = m0 + ty*8 + i;
        if (m < M) {
            #pragma unroll
            for (int j = 0; j < 4; j++)
                C[(size_t)m*ldc + n0 + tx*4 + j] = acc[i][j];
        }
    }
}

// ---------------- epilogue ----------------
__global__ void k_norm_lin(const float* __restrict__ lin_w) {  // one block, 256 thr
    __shared__ float red[8];
    int c = threadIdx.x, lane = c & 31, w = c >> 5;
    for (int k = 0; k < 15; k++) {
        float v = lin_w[k*CC + c];
        float sq = v*v;
        #pragma unroll
        for (int o = 16; o > 0; o >>= 1) sq += __shfl_xor_sync(0xffffffffu, sq, o);
        if (lane == 0) red[w] = sq;
        __syncthreads();
        float tot = 0.f;
        #pragma unroll
        for (int i = 0; i < 8; i++) tot += red[i];
        g_wn[k*CC + c] = v / sqrtf(tot);
        __syncthreads();
    }
}

__global__ void k_out(const float* __restrict__ Z, float* __restrict__ outp) {
    __shared__ float sh[CC];
    __shared__ float red[8];
    int n = blockIdx.x, c = threadIdx.x;
    int lane = c & 31, w = c >> 5;
    float z = Z[(size_t)n*CC + c];
    float sq = z*z;
    #pragma unroll
    for (int o = 16; o > 0; o >>= 1) sq += __shfl_xor_sync(0xffffffffu, sq, o);
    if (lane == 0) red[w] = sq;
    __syncthreads();
    float tot = 0.f;
    #pragma unroll
    for (int i = 0; i < 8; i++) tot += red[i];
    float nrm = fmaxf(sqrtf(tot), 1e-12f);
    float v = z / nrm;
    outp[(size_t)NN*15 + (size_t)n*CC + c] = v;   // cs_r
    sh[c] = v;
    __syncthreads();
    for (int k = w; k < 15; k += 8) {
        float d = 0.f;
        for (int i = lane; i < CC; i += 32) d = fmaf(sh[i], g_wn[k*CC + i], d);
        #pragma unroll
        for (int o = 16; o > 0; o >>= 1) d += __shfl_xor_sync(0xffffffffu, d, o);
        if (lane == 0) outp[(size_t)n*15 + k] = d;   // cs
    }
}

// ---------------- launch ----------------
extern "C" void kernel_launch(void* const* d_in, const int* in_sizes, int n_in,
                              void* d_out, int out_size) {
    const float* image  = (const float*)d_in[0];
    const int*   labels = (const int*)  d_in[1];
    const int*   edges  = (const int*)  d_in[2];
    const float* probas = (const float*)d_in[3];
    const float* feats0 = (const float*)d_in[4];
    const float* feats1 = (const float*)d_in[5];
    const float* W0     = (const float*)d_in[6];
    const float* b0     = (const float*)d_in[7];
    const float* W1     = (const float*)d_in[8];
    const float* b1     = (const float*)d_in[9];
    const float* W2     = (const float*)d_in[10];
    const float* b2     = (const float*)d_in[11];
    const float* lin_w  = (const float*)d_in[12];
    float* outp = (float*)d_out;

    float *pZa, *pZb, *pXw;
    cudaGetSymbolAddress((void**)&pZa, g_Za);
    cudaGetSymbolAddress((void**)&pZb, g_Zb);
    cudaGetSymbolAddress((void**)&pXw, g_xw);

    // init + pooling build
    k_init<<<(NN+255)/256, 256>>>();
    k_build1<<<NPX/256, 256>>>(labels, image);
    k_transpose<<<dim3(HWI/32, CC/32, 8), dim3(32, 8)>>>(feats0, feats1);
    k_scanP<<<1, 1024>>>();
    k_build2<<<NPX/256, 256>>>(labels);
    // heavy SpMM
    k_spmm<<<NN, 256>>>();
    // graph build
    k_edge_w_deg<<<(EE+255)/256, 256>>>(edges, probas);
    k_scanE<<<1, 1024>>>();
    k_edge_scatter<<<(EE+NN+255)/256, 256>>>(edges);
    // layer 1 (image)
    k_x0<<<NN, CC>>>(W0);
    k_agg_relu<<<NN/4, 256>>>(pXw, b0, pZa);
    // layer 2 (feats0)
    k_mix<<<1500, 256>>>(pZa, pZb, 0);
    k_sgemm<<<dim3(CC/64, (NN+127)/128, 1), 256>>>(pZb, W1, pXw, NN, CC, CC, CC, CC, CC);
    k_agg_relu<<<NN/4, 256>>>(pXw, b1, pZa);
    // layer 3 (feats1)
    k_mix<<<1500, 256>>>(pZa, pZb, 64);
    k_sgemm<<<dim3(CC/64, (NN+127)/128, 1), 256>>>(pZb, W2, pXw, NN, CC, CC, CC, CC, CC);
    k_agg_relu<<<NN/4, 256>>>(pXw, b2, pZa);
    // epilogue
    k_norm_lin<<<1, CC>>>(lin_w);
    k_out<<<NN, CC>>>(pZa, outp);
    (void)in_sizes; (void)n_in; (void)out_size;
}

// round 8
// speedup vs baseline: 1.1015x; 1.1015x over previous
#include <cuda_runtime.h>
#include <cuda_fp16.h>
#include <math.h>
#include <stdint.h>

// ---------------- problem constants ----------------
#define BB   4
#define NSP  1500
#define NN   6000          // BB*NSP
#define EE   120000
#define HH   384
#define HWPX (HH*HH)       // 147456
#define NPX  (BB*HWPX)     // 589824
#define HS   96
#define HWI  (HS*HS)       // 9216
#define CC   256
#define NPOOL 512          // feats0 | feats1 columns
#define NENT (2*NPX)       // 1179648 pair-compressed pooling entries
#define CSR_E (EE+NN)      // folded self loops: one entry each, weight 2*dis^2
#define SIGMA_INV 5.0f     // 1/0.2

// ---------------- scratch (device globals; k_init re-inits every call) ----------
__device__ __half g_Bmh[(size_t)BB*HWI*NPOOL + NPOOL]; // 37.7 MB + 1 pad row
__device__ int4  g_ent4[NENT/2];                 // (q,w2,q,w2) pairs, 9.4 MB
__device__ float g_pool[(size_t)NN*NPOOL];
__device__ float g_Za[NN*CC];
__device__ float g_xw[NN*CC];
__device__ float g_cnt[NN];
__device__ float g_sumI[NN*3];
__device__ float g_deg[NN];      // self-loop +2 folded into dis computation
__device__ float g_dis[NN];
__device__ float g_wnn[EE];
__device__ int   g_icnt[NN];
__device__ int   g_ecnt[NN];     // +1 self slot folded into scanE
__device__ int   g_eoff[NN+1];
__device__ int   g_poff[NN+1];
__device__ int   g_efill[NN];
__device__ int   g_pfill[NN];
__device__ int   g_csr_src[CSR_E];
__device__ float g_csr_nrm[CSR_E];
__device__ float g_wn[15*CC];

// ---------------- 0: init (self-healing regardless of prior stream state) -------
__global__ void k_init() {
    int i = blockIdx.x*blockDim.x + threadIdx.x;
    if (i >= NN) return;
    g_icnt[i] = 0; g_ecnt[i] = 0;
    g_efill[i] = 0; g_pfill[i] = 0;
    g_deg[i] = 0.f;
    g_sumI[i*3+0] = 0.f; g_sumI[i*3+1] = 0.f; g_sumI[i*3+2] = 0.f;
}

// ---------------- 1: counts + image sums ----------------
__global__ void k_build1(const int* __restrict__ labels, const float* __restrict__ image) {
    int p = blockIdx.x*blockDim.x + threadIdx.x;
    if (p >= NPX) return;
    int b  = p / HWPX;
    int yx = p % HWPX;
    int s = b*NSP + labels[p];
    atomicAdd(&g_icnt[s], 1);
    atomicAdd(&g_sumI[s*3+0], image[(size_t)(b*3+0)*HWPX + yx]);
    atomicAdd(&g_sumI[s*3+1], image[(size_t)(b*3+1)*HWPX + yx]);
    atomicAdd(&g_sumI[s*3+2], image[(size_t)(b*3+2)*HWPX + yx]);
}

// ---------------- 2: scan pooling counts (x2, warp-shuffle) + cnt float ----------
__global__ void k_scanP() {
    __shared__ int wsum[32];
    int t = threadIdx.x, lane = t & 31, w = t >> 5;
    int loc[6]; int s = 0;
    #pragma unroll
    for (int i = 0; i < 6; i++) {
        int idx = t*6 + i;
        int v = (idx < NN) ? 2*g_icnt[idx] : 0;
        loc[i] = s; s += v;
        if (idx < NN) g_cnt[idx] = (float)(v >> 1);
    }
    int x = s;
    #pragma unroll
    for (int o = 1; o < 32; o <<= 1) {
        int y = __shfl_up_sync(0xffffffffu, x, o);
        if (lane >= o) x += y;
    }
    if (lane == 31) wsum[w] = x;
    __syncthreads();
    if (w == 0) {
        int y = wsum[lane];
        #pragma unroll
        for (int o = 1; o < 32; o <<= 1) {
            int z2 = __shfl_up_sync(0xffffffffu, y, o);
            if (lane >= o) y += z2;
        }
        wsum[lane] = y;
    }
    __syncthreads();
    int base = (w > 0 ? wsum[w-1] : 0) + x - s;   // exclusive prefix of this thread
    #pragma unroll
    for (int i = 0; i < 6; i++) {
        int idx = t*6 + i;
        if (idx < NN) g_poff[idx] = base + loc[i];
    }
    if (t == 1023) g_poff[NN] = base + s;
}

// ---------------- 3: pooling entries, pair-compressed (CSR by superpixel) --------
// Entry = (row q, half2(w_at_q, w_at_q+1)). Two entries per pixel (top/bottom rows).
__global__ void k_build2(const int* __restrict__ labels) {
    int p = blockIdx.x*blockDim.x + threadIdx.x;
    if (p >= NPX) return;
    int b  = p / HWPX;
    int yx = p % HWPX;
    int y = yx / HH, x = yx % HH;
    int s = b*NSP + labels[p];

    const float scale = 95.0f/383.0f;
    float fy = y*scale, fx = x*scale;
    int y0 = (int)floorf(fy); if (y0 > 95) y0 = 95;
    int x0 = (int)floorf(fx); if (x0 > 95) x0 = 95;
    float wy = fy - y0, wx = fx - x0;
    int y1 = min(y0+1, 95);

    float w00 = (1.f-wy)*(1.f-wx), w01 = (1.f-wy)*wx;
    float w10 = wy*(1.f-wx),       w11 = wy*wx;
    if (x0 == 95) { w00 += w01; w01 = 0.f; w10 += w11; w11 = 0.f; }

    int base = b*HWI;
    int pos = g_poff[s] + atomicAdd(&g_pfill[s], 2);   // pos % 2 == 0
    __half2 wt = __floats2half2_rn(w00, w01);
    __half2 wb = __floats2half2_rn(w10, w11);
    int4 e;
    e.x = base + y0*HS + x0;  e.y = *reinterpret_cast<int*>(&wt);
    e.z = base + y1*HS + x0;  e.w = *reinterpret_cast<int*>(&wb);
    g_ent4[pos>>1] = e;
}

// ---------------- 4: feats transpose NCHW -> fp16 (b*9216, 512) ------------------
__global__ void k_transpose(const float* __restrict__ f0, const float* __restrict__ f1) {
    __shared__ float t[32][33];
    int z = blockIdx.z;                 // 0..7
    int b = z & 3;
    int colOff = (z >> 2) * CC;
    const float* __restrict__ src = (z < 4) ? f0 : f1;
    int q0 = blockIdx.x*32, c0 = blockIdx.y*32;
    int tx = threadIdx.x, ty = threadIdx.y;     // 32 x 8
    #pragma unroll
    for (int i = 0; i < 32; i += 8) {
        int c = c0 + ty + i, q = q0 + tx;
        t[ty+i][tx] = src[((size_t)b*CC + c)*HWI + q];
    }
    __syncthreads();
    int tid = ty*32 + tx;
    int qrow = tid >> 3, cg = tid & 7;
    __half2 h0 = __floats2half2_rn(t[cg*4+0][qrow], t[cg*4+1][qrow]);
    __half2 h1 = __floats2half2_rn(t[cg*4+2][qrow], t[cg*4+3][qrow]);
    uint2 o;
    o.x = *reinterpret_cast<unsigned*>(&h0);
    o.y = *reinterpret_cast<unsigned*>(&h1);
    size_t base = ((size_t)b*HWI + q0 + qrow)*NPOOL + colOff + c0 + cg*4;
    *reinterpret_cast<uint2*>(&g_Bmh[base]) = o;
}

// ---------------- 5: sparse pooling SpMM (pair entries) ----------------
// 256 thr = 4 teams x 64 lanes; per entry: two adjacent rows, one half2 weight.
__device__ __forceinline__ void acc8(float* acc, float w, uint4 v) {
    float2 f0 = __half22float2(*(const __half2*)&v.x);
    float2 f1 = __half22float2(*(const __half2*)&v.y);
    float2 f2 = __half22float2(*(const __half2*)&v.z);
    float2 f3 = __half22float2(*(const __half2*)&v.w);
    acc[0] = fmaf(w, f0.x, acc[0]); acc[1] = fmaf(w, f0.y, acc[1]);
    acc[2] = fmaf(w, f1.x, acc[2]); acc[3] = fmaf(w, f1.y, acc[3]);
    acc[4] = fmaf(w, f2.x, acc[4]); acc[5] = fmaf(w, f2.y, acc[5]);
    acc[6] = fmaf(w, f3.x, acc[6]); acc[7] = fmaf(w, f3.y, acc[7]);
}

__global__ void k_spmm() {
    __shared__ int2  sh[256];
    __shared__ float red[4][512];
    int s = blockIdx.x;
    int tid = threadIdx.x;
    int team = tid >> 6, lane = tid & 63;
    int beg = g_poff[s], end = g_poff[s+1];
    const uint4* __restrict__ B4 = reinterpret_cast<const uint4*>(g_Bmh);
    const int2* __restrict__ ent = reinterpret_cast<const int2*>(g_ent4);
    float acc[8];
    #pragma unroll
    for (int i = 0; i < 8; i++) acc[i] = 0.f;

    for (int c0 = beg; c0 < end; c0 += 256) {
        int m = min(256, end - c0);
        __syncthreads();
        if (tid < m) sh[tid] = ent[c0 + tid];
        __syncthreads();
        for (int j = team; j < m; j += 4) {
            int2 e = sh[j];
            float2 wv = __half22float2(*reinterpret_cast<__half2*>(&e.y));
            size_t r = (size_t)e.x*64 + lane;
            uint4 vlo = B4[r];
            uint4 vhi = B4[r + 64];
            acc8(acc, wv.x, vlo);
            acc8(acc, wv.y, vhi);
        }
    }
    #pragma unroll
    for (int i = 0; i < 8; i++) red[team][lane*8+i] = acc[i];
    __syncthreads();
    #pragma unroll
    for (int c = tid; c < 512; c += 256)
        g_pool[(size_t)s*NPOOL + c] = red[0][c] + red[1][c] + red[2][c] + red[3][c];
}

// ---------------- 6: edge weights + degree + per-dst counts ----------------
__global__ void k_edge_w_deg(const int* __restrict__ edges, const float* __restrict__ probas) {
    int e = blockIdx.x*blockDim.x + threadIdx.x;
    if (e >= EE) return;
    int src = edges[e], dst = edges[EE + e];
    float w = expf(-fabsf(probas[src] - probas[dst]) * SIGMA_INV);
    g_wnn[e] = w;
    atomicAdd(&g_deg[dst], w);
    atomicAdd(&g_ecnt[dst], 1);
}

// ---------------- 7: scan edge counts (+1 self slot, warp-shuffle) + dis ---------
__global__ void k_scanE() {
    __shared__ int wsum[32];
    int t = threadIdx.x, lane = t & 31, w = t >> 5;
    int loc[6]; int s = 0;
    #pragma unroll
    for (int i = 0; i < 6; i++) {
        int idx = t*6 + i;
        int v = (idx < NN) ? (g_ecnt[idx] + 1) : 0;
        loc[i] = s; s += v;
        if (idx < NN) {
            float d = g_deg[idx] + 2.0f;
            g_dis[idx] = rsqrtf(fmaxf(d, 1e-30f));
        }
    }
    int x = s;
    #pragma unroll
    for (int o = 1; o < 32; o <<= 1) {
        int y = __shfl_up_sync(0xffffffffu, x, o);
        if (lane >= o) x += y;
    }
    if (lane == 31) wsum[w] = x;
    __syncthreads();
    if (w == 0) {
        int y = wsum[lane];
        #pragma unroll
        for (int o = 1; o < 32; o <<= 1) {
            int z2 = __shfl_up_sync(0xffffffffu, y, o);
            if (lane >= o) y += z2;
        }
        wsum[lane] = y;
    }
    __syncthreads();
    int base = (w > 0 ? wsum[w-1] : 0) + x - s;
    #pragma unroll
    for (int i = 0; i < 6; i++) {
        int idx = t*6 + i;
        if (idx < NN) g_eoff[idx] = base + loc[i];
    }
    if (t == 1023) g_eoff[NN] = base + s;
}

// ---------------- 8: edge CSR scatter (self loop -> last slot, no atomic) ------
__global__ void k_edge_scatter(const int* __restrict__ edges) {
    int i = blockIdx.x*blockDim.x + threadIdx.x;
    if (i >= EE + NN) return;
    if (i < EE) {
        int src = edges[i], dst = edges[EE + i];
        float w = g_wnn[i];
        int j = g_eoff[dst] + atomicAdd(&g_efill[dst], 1);
        g_csr_src[j] = src;
        g_csr_nrm[j] = g_dis[src] * w * g_dis[dst];
    } else {
        int n = i - EE;
        int j = g_eoff[n+1] - 1;
        g_csr_src[j] = n;
        g_csr_nrm[j] = 2.0f * g_dis[n] * g_dis[n];
    }
}

// ---------------- GCN ----------------
__global__ void k_x0(const float* __restrict__ W0) {   // xw = (sumI/cnt) @ W0 (K=3)
    __shared__ float z0[3];
    int n = blockIdx.x, c = threadIdx.x;
    if (c < 3) z0[c] = g_sumI[n*3+c] / fmaxf(g_cnt[n], 1.0f);
    __syncthreads();
    g_xw[(size_t)n*CC + c] = z0[0]*W0[c] + z0[1]*W0[CC+c] + z0[2]*W0[2*CC+c];
}

// 256 thr = 4 teams x 64 lanes; lane owns 4 cols via float4. grid = NN/4.
__global__ void k_agg_relu(const float* __restrict__ xw, const float* __restrict__ bias,
                           float* __restrict__ out) {
    int tid = threadIdx.x;
    int team = tid >> 6, lane = tid & 63;
    int n = blockIdx.x*4 + team;
    const float4* __restrict__ xw4 = reinterpret_cast<const float4*>(xw);
    float4 bv = reinterpret_cast<const float4*>(bias)[lane];
    int s = g_eoff[n], e = g_eoff[n+1];
    float4 acc = make_float4(0.f,0.f,0.f,0.f);
    for (int j = s; j < e; j++) {
        int   sc = __ldg(&g_csr_src[j]);
        float nr = __ldg(&g_csr_nrm[j]);
        float4 v = xw4[(size_t)sc*64 + lane];
        acc.x = fmaf(nr, v.x, acc.x); acc.y = fmaf(nr, v.y, acc.y);
        acc.z = fmaf(nr, v.z, acc.z); acc.w = fmaf(nr, v.w, acc.w);
    }
    float4 r;
    r.x = fmaxf(acc.x + bv.x, 0.f); r.y = fmaxf(acc.y + bv.y, 0.f);
    r.z = fmaxf(acc.z + bv.z, 0.f); r.w = fmaxf(acc.w + bv.w, 0.f);
    reinterpret_cast<float4*>(out)[(size_t)n*64 + lane] = r;
}

// ---------------- SGEMM with fused mix A-operand ----------------
// C = A' @ B, A'[m][k] = 0.5*pool[m][offF+k]/cnt[m] + 0.5*Za[m][k]
// M=6000 (guarded), N=K=256. BM=128 BN=64 BK=8, 256 threads, 8x4 per-thread tile.
__global__ void k_sgemm_mix(const float* __restrict__ Za, const float* __restrict__ B,
                            float* __restrict__ C, int offF) {
    __shared__ float As[8][128];
    __shared__ float Bs[8][64];
    int tid = threadIdx.x;
    int tx = tid & 15, ty = tid >> 4;
    int m0 = blockIdx.y*128, n0 = blockIdx.x*64;
    float acc[8][4];
    #pragma unroll
    for (int i=0;i<8;i++)
        #pragma unroll
        for (int j=0;j<4;j++) acc[i][j]=0.f;

    int a_m = tid >> 1;          // 0..127
    int a_k = (tid & 1) * 4;     // 0 or 4
    int b_k = tid >> 5;
    int b_n = (tid & 31) * 2;
    int m = m0 + a_m;
    bool mok = (m < NN);
    float inv = mok ? 0.5f / fmaxf(g_cnt[m], 1.0f) : 0.f;
    const float* poolRow = g_pool + (size_t)(mok ? m : 0)*NPOOL + offF;
    const float* zaRow   = Za     + (size_t)(mok ? m : 0)*CC;

    for (int kt = 0; kt < CC; kt += 8) {
        float4 av = make_float4(0.f,0.f,0.f,0.f);
        if (mok) {
            float4 hp = *reinterpret_cast<const float4*>(poolRow + kt + a_k);
            float4 za = *reinterpret_cast<const float4*>(zaRow   + kt + a_k);
            av.x = hp.x*inv + 0.5f*za.x; av.y = hp.y*inv + 0.5f*za.y;
            av.z = hp.z*inv + 0.5f*za.z; av.w = hp.w*inv + 0.5f*za.w;
        }
        As[a_k+0][a_m]=av.x; As[a_k+1][a_m]=av.y;
        As[a_k+2][a_m]=av.z; As[a_k+3][a_m]=av.w;
        float2 bv = *reinterpret_cast<const float2*>(B + (size_t)(kt+b_k)*CC + n0 + b_n);
        Bs[b_k][b_n]=bv.x; Bs[b_k][b_n+1]=bv.y;
        __syncthreads();
        #pragma unroll
        for (int k = 0; k < 8; k++) {
            float ar[8], br[4];
            #pragma unroll
            for (int i=0;i<8;i++) ar[i]=As[k][ty*8+i];
            #pragma unroll
            for (int j=0;j<4;j++) br[j]=Bs[k][tx*4+j];
            #pragma unroll
            for (int i=0;i<8;i++)
                #pragma unroll
                for (int j=0;j<4;j++) acc[i][j] = fmaf(ar[i], br[j], acc[i][j]);
        }
        __syncthreads();
    }
    #pragma unroll
    for (int i = 0; i < 8; i++) {
        int mm = m0 + ty*8 + i;
        if (mm < NN) {
            #pragma unroll
            for (int j = 0; j < 4; j++)
                C[(size_t)mm*CC + n0 + tx*4 + j] = acc[i][j];
        }
    }
}

// ---------------- epilogue ----------------
__global__ void k_norm_lin(const float* __restrict__ lin_w) {  // one block, 256 thr
    __shared__ float red[8];
    int c = threadIdx.x, lane = c & 31, w = c >> 5;
    for (int k = 0; k < 15; k++) {
        float v = lin_w[k*CC + c];
        float sq = v*v;
        #pragma unroll
        for (int o = 16; o > 0; o >>= 1) sq += __shfl_xor_sync(0xffffffffu, sq, o);
        if (lane == 0) red[w] = sq;
        __syncthreads();
        float tot = 0.f;
        #pragma unroll
        for (int i = 0; i < 8; i++) tot += red[i];
        g_wn[k*CC + c] = v / sqrtf(tot);
        __syncthreads();
    }
}

__global__ void k_out(const float* __restrict__ Z, float* __restrict__ outp) {
    __shared__ float sh[CC];
    __shared__ float red[8];
    int n = blockIdx.x, c = threadIdx.x;
    int lane = c & 31, w = c >> 5;
    float z = Z[(size_t)n*CC + c];
    float sq = z*z;
    #pragma unroll
    for (int o = 16; o > 0; o >>= 1) sq += __shfl_xor_sync(0xffffffffu, sq, o);
    if (lane == 0) red[w] = sq;
    __syncthreads();
    float tot = 0.f;
    #pragma unroll
    for (int i = 0; i < 8; i++) tot += red[i];
    float nrm = fmaxf(sqrtf(tot), 1e-12f);
    float v = z / nrm;
    outp[(size_t)NN*15 + (size_t)n*CC + c] = v;   // cs_r
    sh[c] = v;
    __syncthreads();
    for (int k = w; k < 15; k += 8) {
        float d = 0.f;
        for (int i = lane; i < CC; i += 32) d = fmaf(sh[i], g_wn[k*CC + i], d);
        #pragma unroll
        for (int o = 16; o > 0; o >>= 1) d += __shfl_xor_sync(0xffffffffu, d, o);
        if (lane == 0) outp[(size_t)n*15 + k] = d;   // cs
    }
}

// ---------------- launch ----------------
extern "C" void kernel_launch(void* const* d_in, const int* in_sizes, int n_in,
                              void* d_out, int out_size) {
    const float* image  = (const float*)d_in[0];
    const int*   labels = (const int*)  d_in[1];
    const int*   edges  = (const int*)  d_in[2];
    const float* probas = (const float*)d_in[3];
    const float* feats0 = (const float*)d_in[4];
    const float* feats1 = (const float*)d_in[5];
    const float* W0     = (const float*)d_in[6];
    const float* b0     = (const float*)d_in[7];
    const float* W1     = (const float*)d_in[8];
    const float* b1     = (const float*)d_in[9];
    const float* W2     = (const float*)d_in[10];
    const float* b2     = (const float*)d_in[11];
    const float* lin_w  = (const float*)d_in[12];
    float* outp = (float*)d_out;

    float *pZa, *pXw;
    cudaGetSymbolAddress((void**)&pZa, g_Za);
    cudaGetSymbolAddress((void**)&pXw, g_xw);

    // 1-4: init + pooling build (launch #4 = k_build2, lands in ncu window)
    k_init<<<(NN+255)/256, 256>>>();
    k_build1<<<NPX/256, 256>>>(labels, image);
    k_scanP<<<1, 1024>>>();
    k_build2<<<NPX/256, 256>>>(labels);
    // 5-6: transpose + heavy SpMM
    k_transpose<<<dim3(HWI/32, CC/32, 8), dim3(32, 8)>>>(feats0, feats1);
    k_spmm<<<NN, 256>>>();
    // 7-9: graph build
    k_edge_w_deg<<<(EE+255)/256, 256>>>(edges, probas);
    k_scanE<<<1, 1024>>>();
    k_edge_scatter<<<(EE+NN+255)/256, 256>>>(edges);
    // 10: epilogue prep (independent; fills bubble)
    k_norm_lin<<<1, CC>>>(lin_w);
    // 11-12: layer 1 (image)
    k_x0<<<NN, CC>>>(W0);
    k_agg_relu<<<NN/4, 256>>>(pXw, b0, pZa);
    // 13-14: layer 2 (feats0) — mix fused into GEMM
    k_sgemm_mix<<<dim3(CC/64, (NN+127)/128), 256>>>(pZa, W1, pXw, 0);
    k_agg_relu<<<NN/4, 256>>>(pXw, b1, pZa);
    // 15-16: layer 3 (feats1)
    k_sgemm_mix<<<dim3(CC/64, (NN+127)/128), 256>>>(pZa, W2, pXw, CC);
    k_agg_relu<<<NN/4, 256>>>(pXw, b2, pZa);
    // 17: output
    k_out<<<NN, CC>>>(pZa, outp);
    (void)in_sizes; (void)n_in; (void)out_size;
}

// round 9
// speedup vs baseline: 1.1481x; 1.0423x over previous
#include <cuda_runtime.h>
#include <cuda_fp16.h>
#include <math.h>
#include <stdint.h>

// ---------------- problem constants ----------------
#define BB   4
#define NSP  1500
#define NN   6000          // BB*NSP
#define EE   120000
#define HH   384
#define HWPX (HH*HH)       // 147456
#define NPX  (BB*HWPX)     // 589824
#define HS   96
#define HWI  (HS*HS)       // 9216
#define CC   256
#define NPOOL 512          // feats0 | feats1 columns
#define NENT (2*NPX)       // 1179648 pair-compressed pooling entries
#define CSR_E (EE+NN)      // folded self loops: one entry each, weight 2*dis^2
#define SIGMA_INV 5.0f     // 1/0.2

// ---------------- scratch (device globals; k_init re-inits every call) ----------
__device__ __half g_Bmh[(size_t)BB*HWI*NPOOL + NPOOL]; // 37.7 MB + 1 pad row
__device__ int4  g_ent4[NENT/2];                 // (q,w2,q,w2) pairs, 9.4 MB
__device__ float g_pool[(size_t)NN*NPOOL];
__device__ float g_Za[NN*CC];
__device__ float g_xw[NN*CC];
__device__ float g_cnt[NN];
__device__ float g_sumI[NN*3];
__device__ float g_deg[NN];      // self-loop +2 folded into dis computation
__device__ float g_dis[NN];
__device__ float g_wnn[EE];
__device__ int   g_icnt[NN];
__device__ int   g_ecnt[NN];     // +1 self slot folded into scanE
__device__ int   g_eoff[NN+1];
__device__ int   g_poff[NN+1];
__device__ int   g_efill[NN];
__device__ int   g_pfill[NN];
__device__ int   g_csr_src[CSR_E];
__device__ float g_csr_nrm[CSR_E];
__device__ float g_wn[15*CC];

// ---------------- 0: init (self-healing regardless of prior stream state) -------
__global__ void k_init() {
    int i = blockIdx.x*blockDim.x + threadIdx.x;
    if (i >= NN) return;
    g_icnt[i] = 0; g_ecnt[i] = 0;
    g_efill[i] = 0; g_pfill[i] = 0;
    g_deg[i] = 0.f;
    g_sumI[i*3+0] = 0.f; g_sumI[i*3+1] = 0.f; g_sumI[i*3+2] = 0.f;
}

// ---------------- 1: counts + image sums (4 batches per thread, same yx) --------
__global__ void k_build1(const int* __restrict__ labels, const float* __restrict__ image) {
    int yx = blockIdx.x*blockDim.x + threadIdx.x;   // 0..HWPX-1
    int s0 = labels[0*HWPX + yx] + 0*NSP;
    int s1 = labels[1*HWPX + yx] + 1*NSP;
    int s2 = labels[2*HWPX + yx] + 2*NSP;
    int s3 = labels[3*HWPX + yx] + 3*NSP;
    atomicAdd(&g_icnt[s0], 1);
    atomicAdd(&g_icnt[s1], 1);
    atomicAdd(&g_icnt[s2], 1);
    atomicAdd(&g_icnt[s3], 1);
    #pragma unroll
    for (int c = 0; c < 3; c++) {
        atomicAdd(&g_sumI[s0*3+c], image[(size_t)(0*3+c)*HWPX + yx]);
        atomicAdd(&g_sumI[s1*3+c], image[(size_t)(1*3+c)*HWPX + yx]);
        atomicAdd(&g_sumI[s2*3+c], image[(size_t)(2*3+c)*HWPX + yx]);
        atomicAdd(&g_sumI[s3*3+c], image[(size_t)(3*3+c)*HWPX + yx]);
    }
}

// ---------------- 2: scan pooling counts (x2, warp-shuffle) + cnt float ----------
__global__ void k_scanP() {
    __shared__ int wsum[32];
    int t = threadIdx.x, lane = t & 31, w = t >> 5;
    int loc[6]; int s = 0;
    #pragma unroll
    for (int i = 0; i < 6; i++) {
        int idx = t*6 + i;
        int v = (idx < NN) ? 2*g_icnt[idx] : 0;
        loc[i] = s; s += v;
        if (idx < NN) g_cnt[idx] = (float)(v >> 1);
    }
    int x = s;
    #pragma unroll
    for (int o = 1; o < 32; o <<= 1) {
        int y = __shfl_up_sync(0xffffffffu, x, o);
        if (lane >= o) x += y;
    }
    if (lane == 31) wsum[w] = x;
    __syncthreads();
    if (w == 0) {
        int y = wsum[lane];
        #pragma unroll
        for (int o = 1; o < 32; o <<= 1) {
            int z2 = __shfl_up_sync(0xffffffffu, y, o);
            if (lane >= o) y += z2;
        }
        wsum[lane] = y;
    }
    __syncthreads();
    int base = (w > 0 ? wsum[w-1] : 0) + x - s;   // exclusive prefix of this thread
    #pragma unroll
    for (int i = 0; i < 6; i++) {
        int idx = t*6 + i;
        if (idx < NN) g_poff[idx] = base + loc[i];
    }
    if (t == 1023) g_poff[NN] = base + s;
}

// ---------------- 3: pooling entries (4 batches per thread, bilinear once) -------
__global__ void k_build2(const int* __restrict__ labels) {
    int yx = blockIdx.x*blockDim.x + threadIdx.x;   // 0..HWPX-1
    int y = yx / HH, x = yx % HH;

    const float scale = 95.0f/383.0f;
    float fy = y*scale, fx = x*scale;
    int y0 = (int)floorf(fy); if (y0 > 95) y0 = 95;
    int x0 = (int)floorf(fx); if (x0 > 95) x0 = 95;
    float wy = fy - y0, wx = fx - x0;
    int y1 = min(y0+1, 95);

    float w00 = (1.f-wy)*(1.f-wx), w01 = (1.f-wy)*wx;
    float w10 = wy*(1.f-wx),       w11 = wy*wx;
    if (x0 == 95) { w00 += w01; w01 = 0.f; w10 += w11; w11 = 0.f; }
    __half2 wt = __floats2half2_rn(w00, w01);
    __half2 wb = __floats2half2_rn(w10, w11);
    int wti = *reinterpret_cast<int*>(&wt);
    int wbi = *reinterpret_cast<int*>(&wb);
    int qt = y0*HS + x0, qb = y1*HS + x0;

    #pragma unroll
    for (int b = 0; b < BB; b++) {
        int s = b*NSP + labels[b*HWPX + yx];
        int pos = g_poff[s] + atomicAdd(&g_pfill[s], 2);   // pos % 2 == 0
        int4 e;
        e.x = b*HWI + qt;  e.y = wti;
        e.z = b*HWI + qb;  e.w = wbi;
        g_ent4[pos>>1] = e;
    }
}

// ---------------- 4: feats transpose NCHW -> fp16 (b*9216, 512) ------------------
__global__ void k_transpose(const float* __restrict__ f0, const float* __restrict__ f1) {
    __shared__ float t[32][33];
    int z = blockIdx.z;                 // 0..7
    int b = z & 3;
    int colOff = (z >> 2) * CC;
    const float* __restrict__ src = (z < 4) ? f0 : f1;
    int q0 = blockIdx.x*32, c0 = blockIdx.y*32;
    int tx = threadIdx.x, ty = threadIdx.y;     // 32 x 8
    #pragma unroll
    for (int i = 0; i < 32; i += 8) {
        int c = c0 + ty + i, q = q0 + tx;
        t[ty+i][tx] = src[((size_t)b*CC + c)*HWI + q];
    }
    __syncthreads();
    int tid = ty*32 + tx;
    int qrow = tid >> 3, cg = tid & 7;
    __half2 h0 = __floats2half2_rn(t[cg*4+0][qrow], t[cg*4+1][qrow]);
    __half2 h1 = __floats2half2_rn(t[cg*4+2][qrow], t[cg*4+3][qrow]);
    uint2 o;
    o.x = *reinterpret_cast<unsigned*>(&h0);
    o.y = *reinterpret_cast<unsigned*>(&h1);
    size_t base = ((size_t)b*HWI + q0 + qrow)*NPOOL + colOff + c0 + cg*4;
    *reinterpret_cast<uint2*>(&g_Bmh[base]) = o;
}

// ---------------- 5: sparse pooling SpMM (pair entries) ----------------
// 256 thr = 4 teams x 64 lanes; per entry: two adjacent rows, one half2 weight.
__device__ __forceinline__ void acc8(float* acc, float w, uint4 v) {
    float2 f0 = __half22float2(*(const __half2*)&v.x);
    float2 f1 = __half22float2(*(const __half2*)&v.y);
    float2 f2 = __half22float2(*(const __half2*)&v.z);
    float2 f3 = __half22float2(*(const __half2*)&v.w);
    acc[0] = fmaf(w, f0.x, acc[0]); acc[1] = fmaf(w, f0.y, acc[1]);
    acc[2] = fmaf(w, f1.x, acc[2]); acc[3] = fmaf(w, f1.y, acc[3]);
    acc[4] = fmaf(w, f2.x, acc[4]); acc[5] = fmaf(w, f2.y, acc[5]);
    acc[6] = fmaf(w, f3.x, acc[6]); acc[7] = fmaf(w, f3.y, acc[7]);
}

__global__ void k_spmm() {
    __shared__ int2  sh[256];
    __shared__ float red[4][512];
    int s = blockIdx.x;
    int tid = threadIdx.x;
    int team = tid >> 6, lane = tid & 63;
    int beg = g_poff[s], end = g_poff[s+1];
    const uint4* __restrict__ B4 = reinterpret_cast<const uint4*>(g_Bmh);
    const int2* __restrict__ ent = reinterpret_cast<const int2*>(g_ent4);
    float acc[8];
    #pragma unroll
    for (int i = 0; i < 8; i++) acc[i] = 0.f;

    for (int c0 = beg; c0 < end; c0 += 256) {
        int m = min(256, end - c0);
        __syncthreads();
        if (tid < m) sh[tid] = ent[c0 + tid];
        __syncthreads();
        for (int j = team; j < m; j += 4) {
            int2 e = sh[j];
            float2 wv = __half22float2(*reinterpret_cast<__half2*>(&e.y));
            size_t r = (size_t)e.x*64 + lane;
            uint4 vlo = B4[r];
            uint4 vhi = B4[r + 64];
            acc8(acc, wv.x, vlo);
            acc8(acc, wv.y, vhi);
        }
    }
    #pragma unroll
    for (int i = 0; i < 8; i++) red[team][lane*8+i] = acc[i];
    __syncthreads();
    #pragma unroll
    for (int c = tid; c < 512; c += 256)
        g_pool[(size_t)s*NPOOL + c] = red[0][c] + red[1][c] + red[2][c] + red[3][c];
}

// ---------------- 6: edge weights + degree + per-dst counts ----------------
__global__ void k_edge_w_deg(const int* __restrict__ edges, const float* __restrict__ probas) {
    int e = blockIdx.x*blockDim.x + threadIdx.x;
    if (e >= EE) return;
    int src = edges[e], dst = edges[EE + e];
    float w = expf(-fabsf(probas[src] - probas[dst]) * SIGMA_INV);
    g_wnn[e] = w;
    atomicAdd(&g_deg[dst], w);
    atomicAdd(&g_ecnt[dst], 1);
}

// ---------------- 7: scan edge counts (+1 self slot, warp-shuffle) + dis ---------
__global__ void k_scanE() {
    __shared__ int wsum[32];
    int t = threadIdx.x, lane = t & 31, w = t >> 5;
    int loc[6]; int s = 0;
    #pragma unroll
    for (int i = 0; i < 6; i++) {
        int idx = t*6 + i;
        int v = (idx < NN) ? (g_ecnt[idx] + 1) : 0;
        loc[i] = s; s += v;
        if (idx < NN) {
            float d = g_deg[idx] + 2.0f;
            g_dis[idx] = rsqrtf(fmaxf(d, 1e-30f));
        }
    }
    int x = s;
    #pragma unroll
    for (int o = 1; o < 32; o <<= 1) {
        int y = __shfl_up_sync(0xffffffffu, x, o);
        if (lane >= o) x += y;
    }
    if (lane == 31) wsum[w] = x;
    __syncthreads();
    if (w == 0) {
        int y = wsum[lane];
        #pragma unroll
        for (int o = 1; o < 32; o <<= 1) {
            int z2 = __shfl_up_sync(0xffffffffu, y, o);
            if (lane >= o) y += z2;
        }
        wsum[lane] = y;
    }
    __syncthreads();
    int base = (w > 0 ? wsum[w-1] : 0) + x - s;
    #pragma unroll
    for (int i = 0; i < 6; i++) {
        int idx = t*6 + i;
        if (idx < NN) g_eoff[idx] = base + loc[i];
    }
    if (t == 1023) g_eoff[NN] = base + s;
}

// ---------------- 8: edge CSR scatter (self loop -> last slot, no atomic) ------
__global__ void k_edge_scatter(const int* __restrict__ edges) {
    int i = blockIdx.x*blockDim.x + threadIdx.x;
    if (i >= EE + NN) return;
    if (i < EE) {
        int src = edges[i], dst = edges[EE + i];
        float w = g_wnn[i];
        int j = g_eoff[dst] + atomicAdd(&g_efill[dst], 1);
        g_csr_src[j] = src;
        g_csr_nrm[j] = g_dis[src] * w * g_dis[dst];
    } else {
        int n = i - EE;
        int j = g_eoff[n+1] - 1;
        g_csr_src[j] = n;
        g_csr_nrm[j] = 2.0f * g_dis[n] * g_dis[n];
    }
}

// ---------------- GCN ----------------
__global__ void k_x0(const float* __restrict__ W0) {   // xw = (sumI/cnt) @ W0 (K=3)
    __shared__ float z0[3];
    int n = blockIdx.x, c = threadIdx.x;
    if (c < 3) z0[c] = g_sumI[n*3+c] / fmaxf(g_cnt[n], 1.0f);
    __syncthreads();
    g_xw[(size_t)n*CC + c] = z0[0]*W0[c] + z0[1]*W0[CC+c] + z0[2]*W0[2*CC+c];
}

// 256 thr = 4 teams x 64 lanes; lane owns 4 cols via float4. grid = NN/4.
// 2-way unrolled CSR loop, dual accumulators for MLP.
__global__ void k_agg_relu(const float* __restrict__ xw, const float* __restrict__ bias,
                           float* __restrict__ out) {
    int tid = threadIdx.x;
    int team = tid >> 6, lane = tid & 63;
    int n = blockIdx.x*4 + team;
    const float4* __restrict__ xw4 = reinterpret_cast<const float4*>(xw);
    float4 bv = reinterpret_cast<const float4*>(bias)[lane];
    int s = g_eoff[n], e = g_eoff[n+1];
    float4 a0 = make_float4(0.f,0.f,0.f,0.f);
    float4 a1 = make_float4(0.f,0.f,0.f,0.f);
    int j = s;
    for (; j + 1 < e; j += 2) {
        int   sc0 = __ldg(&g_csr_src[j]);
        int   sc1 = __ldg(&g_csr_src[j+1]);
        float nr0 = __ldg(&g_csr_nrm[j]);
        float nr1 = __ldg(&g_csr_nrm[j+1]);
        float4 v0 = xw4[(size_t)sc0*64 + lane];
        float4 v1 = xw4[(size_t)sc1*64 + lane];
        a0.x = fmaf(nr0, v0.x, a0.x); a0.y = fmaf(nr0, v0.y, a0.y);
        a0.z = fmaf(nr0, v0.z, a0.z); a0.w = fmaf(nr0, v0.w, a0.w);
        a1.x = fmaf(nr1, v1.x, a1.x); a1.y = fmaf(nr1, v1.y, a1.y);
        a1.z = fmaf(nr1, v1.z, a1.z); a1.w = fmaf(nr1, v1.w, a1.w);
    }
    if (j < e) {
        int   sc0 = __ldg(&g_csr_src[j]);
        float nr0 = __ldg(&g_csr_nrm[j]);
        float4 v0 = xw4[(size_t)sc0*64 + lane];
        a0.x = fmaf(nr0, v0.x, a0.x); a0.y = fmaf(nr0, v0.y, a0.y);
        a0.z = fmaf(nr0, v0.z, a0.z); a0.w = fmaf(nr0, v0.w, a0.w);
    }
    float4 r;
    r.x = fmaxf(a0.x + a1.x + bv.x, 0.f); r.y = fmaxf(a0.y + a1.y + bv.y, 0.f);
    r.z = fmaxf(a0.z + a1.z + bv.z, 0.f); r.w = fmaxf(a0.w + a1.w + bv.w, 0.f);
    reinterpret_cast<float4*>(out)[(size_t)n*64 + lane] = r;
}

// ---------------- SGEMM with fused mix A-operand ----------------
// C = A' @ B, A'[m][k] = 0.5*pool[m][offF+k]/cnt[m] + 0.5*Za[m][k]
__global__ void k_sgemm_mix(const float* __restrict__ Za, const float* __restrict__ B,
                            float* __restrict__ C, int offF) {
    __shared__ float As[8][128];
    __shared__ float Bs[8][64];
    int tid = threadIdx.x;
    int tx = tid & 15, ty = tid >> 4;
    int m0 = blockIdx.y*128, n0 = blockIdx.x*64;
    float acc[8][4];
    #pragma unroll
    for (int i=0;i<8;i++)
        #pragma unroll
        for (int j=0;j<4;j++) acc[i][j]=0.f;

    int a_m = tid >> 1;          // 0..127
    int a_k = (tid & 1) * 4;     // 0 or 4
    int b_k = tid >> 5;
    int b_n = (tid & 31) * 2;
    int m = m0 + a_m;
    bool mok = (m < NN);
    float inv = mok ? 0.5f / fmaxf(g_cnt[m], 1.0f) : 0.f;
    const float* poolRow = g_pool + (size_t)(mok ? m : 0)*NPOOL + offF;
    const float* zaRow   = Za     + (size_t)(mok ? m : 0)*CC;

    for (int kt = 0; kt < CC; kt += 8) {
        float4 av = make_float4(0.f,0.f,0.f,0.f);
        if (mok) {
            float4 hp = *reinterpret_cast<const float4*>(poolRow + kt + a_k);
            float4 za = *reinterpret_cast<const float4*>(zaRow   + kt + a_k);
            av.x = hp.x*inv + 0.5f*za.x; av.y = hp.y*inv + 0.5f*za.y;
            av.z = hp.z*inv + 0.5f*za.z; av.w = hp.w*inv + 0.5f*za.w;
        }
        As[a_k+0][a_m]=av.x; As[a_k+1][a_m]=av.y;
        As[a_k+2][a_m]=av.z; As[a_k+3][a_m]=av.w;
        float2 bv = *reinterpret_cast<const float2*>(B + (size_t)(kt+b_k)*CC + n0 + b_n);
        Bs[b_k][b_n]=bv.x; Bs[b_k][b_n+1]=bv.y;
        __syncthreads();
        #pragma unroll
        for (int k = 0; k < 8; k++) {
            float ar[8], br[4];
            #pragma unroll
            for (int i=0;i<8;i++) ar[i]=As[k][ty*8+i];
            #pragma unroll
            for (int j=0;j<4;j++) br[j]=Bs[k][tx*4+j];
            #pragma unroll
            for (int i=0;i<8;i++)
                #pragma unroll
                for (int j=0;j<4;j++) acc[i][j] = fmaf(ar[i], br[j], acc[i][j]);
        }
        __syncthreads();
    }
    #pragma unroll
    for (int i = 0; i < 8; i++) {
        int mm = m0 + ty*8 + i;
        if (mm < NN) {
            #pragma unroll
            for (int j = 0; j < 4; j++)
                C[(size_t)mm*CC + n0 + tx*4 + j] = acc[i][j];
        }
    }
}

// ---------------- epilogue ----------------
__global__ void k_norm_lin(const float* __restrict__ lin_w) {  // one block, 256 thr
    __shared__ float red[8];
    int c = threadIdx.x, lane = c & 31, w = c >> 5;
    for (int k = 0; k < 15; k++) {
        float v = lin_w[k*CC + c];
        float sq = v*v;
        #pragma unroll
        for (int o = 16; o > 0; o >>= 1) sq += __shfl_xor_sync(0xffffffffu, sq, o);
        if (lane == 0) red[w] = sq;
        __syncthreads();
        float tot = 0.f;
        #pragma unroll
        for (int i = 0; i < 8; i++) tot += red[i];
        g_wn[k*CC + c] = v / sqrtf(tot);
        __syncthreads();
    }
}

__global__ void k_out(const float* __restrict__ Z, float* __restrict__ outp) {
    __shared__ float sh[CC];
    __shared__ float red[8];
    int n = blockIdx.x, c = threadIdx.x;
    int lane = c & 31, w = c >> 5;
    float z = Z[(size_t)n*CC + c];
    float sq = z*z;
    #pragma unroll
    for (int o = 16; o > 0; o >>= 1) sq += __shfl_xor_sync(0xffffffffu, sq, o);
    if (lane == 0) red[w] = sq;
    __syncthreads();
    float tot = 0.f;
    #pragma unroll
    for (int i = 0; i < 8; i++) tot += red[i];
    float nrm = fmaxf(sqrtf(tot), 1e-12f);
    float v = z / nrm;
    outp[(size_t)NN*15 + (size_t)n*CC + c] = v;   // cs_r
    sh[c] = v;
    __syncthreads();
    for (int k = w; k < 15; k += 8) {
        float d = 0.f;
        for (int i = lane; i < CC; i += 32) d = fmaf(sh[i], g_wn[k*CC + i], d);
        #pragma unroll
        for (int o = 16; o > 0; o >>= 1) d += __shfl_xor_sync(0xffffffffu, d, o);
        if (lane == 0) outp[(size_t)n*15 + k] = d;   // cs
    }
}

// ---------------- launch ----------------
extern "C" void kernel_launch(void* const* d_in, const int* in_sizes, int n_in,
                              void* d_out, int out_size) {
    const float* image  = (const float*)d_in[0];
    const int*   labels = (const int*)  d_in[1];
    const int*   edges  = (const int*)  d_in[2];
    const float* probas = (const float*)d_in[3];
    const float* feats0 = (const float*)d_in[4];
    const float* feats1 = (const float*)d_in[5];
    const float* W0     = (const float*)d_in[6];
    const float* b0     = (const float*)d_in[7];
    const float* W1     = (const float*)d_in[8];
    const float* b1     = (const float*)d_in[9];
    const float* W2     = (const float*)d_in[10];
    const float* b2     = (const float*)d_in[11];
    const float* lin_w  = (const float*)d_in[12];
    float* outp = (float*)d_out;

    float *pZa, *pXw;
    cudaGetSymbolAddress((void**)&pZa, g_Za);
    cudaGetSymbolAddress((void**)&pXw, g_xw);

    // 1-4: init + pooling build (launch #4 = k_build2, lands in ncu window)
    k_init<<<(NN+255)/256, 256>>>();
    k_build1<<<HWPX/256, 256>>>(labels, image);
    k_scanP<<<1, 1024>>>();
    k_build2<<<HWPX/256, 256>>>(labels);
    // 5-6: transpose + heavy SpMM
    k_transpose<<<dim3(HWI/32, CC/32, 8), dim3(32, 8)>>>(feats0, feats1);
    k_spmm<<<NN, 256>>>();
    // 7-9: graph build
    k_edge_w_deg<<<(EE+255)/256, 256>>>(edges, probas);
    k_scanE<<<1, 1024>>>();
    k_edge_scatter<<<(EE+NN+255)/256, 256>>>(edges);
    // 10: epilogue prep (independent; fills bubble)
    k_norm_lin<<<1, CC>>>(lin_w);
    // 11-12: layer 1 (image)
    k_x0<<<NN, CC>>>(W0);
    k_agg_relu<<<NN/4, 256>>>(pXw, b0, pZa);
    // 13-14: layer 2 (feats0) — mix fused into GEMM
    k_sgemm_mix<<<dim3(CC/64, (NN+127)/128), 256>>>(pZa, W1, pXw, 0);
    k_agg_relu<<<NN/4, 256>>>(pXw, b1, pZa);
    // 15-16: layer 3 (feats1)
    k_sgemm_mix<<<dim3(CC/64, (NN+127)/128), 256>>>(pZa, W2, pXw, CC);
    k_agg_relu<<<NN/4, 256>>>(pXw, b2, pZa);
    // 17: output
    k_out<<<NN, CC>>>(pZa, outp);
    (void)in_sizes; (void)n_in; (void)out_size;
}